// round 4
// baseline (speedup 1.0000x reference)
#include <cuda_runtime.h>
#include <cuda_bf16.h>

#define IMG_W 1024
#define IMG_H 1024
#define KS 15
#define NB 32

typedef unsigned long long u64;

// ---- packed fp32x2 helpers (Blackwell, PTX-only) ----
__device__ __forceinline__ u64 pack2(float lo, float hi) {
    u64 r;
    asm("mov.b64 %0, {%1, %2};" : "=l"(r) : "f"(lo), "f"(hi));
    return r;
}
__device__ __forceinline__ void unpack2(u64 v, float& lo, float& hi) {
    asm("mov.b64 {%0, %1}, %2;" : "=f"(lo), "=f"(hi) : "l"(v));
}
__device__ __forceinline__ void fma2(u64& d, u64 a, u64 b) {
    asm("fma.rn.f32x2 %0, %1, %2, %3;" : "=l"(d) : "l"(a), "l"(b), "l"(d));
}
__device__ __forceinline__ u64 add2(u64 a, u64 b) {
    u64 r;
    asm("add.rn.f32x2 %0, %1, %2;" : "=l"(r) : "l"(a), "l"(b));
    return r;
}

// Thread: 2 px (one f32x2 pair) x 8 output rows. Lanes x-contiguous:
// warp covers 64 consecutive px. Block 256 thr = 8 warps: 2 in x, 4 in y.
// Block tile: 128 px (x) * 32 rows (y). Grid (8, 32, 32).
//
// Weights live ENTIRELY in registers: the Airy kernel is symmetric in both
// dx (k[dy][7-e]==k[dy][7+e]) and dy (k[dy]==k[14-dy]), so 8 rows x 8 folded
// taps = 64 (w,w) pairs = 128 regs. Inner loop is pure FFMA2 vs registers.
__global__ __launch_bounds__(256, 1) void stem_conv_roll(
    const float* __restrict__ in, const float* __restrict__ kern,
    const int* __restrict__ shifts, float* __restrict__ out)
{
    // One-time register preload of folded weights (uniform broadcast LDGs).
    u64 wreg[8][8];
    #pragma unroll
    for (int wr = 0; wr < 8; ++wr)
        #pragma unroll
        for (int e = 0; e < 8; ++e) {
            float w = __ldg(kern + wr * KS + 7 + e);
            wreg[wr][e] = pack2(w, w);
        }

    const int lane = threadIdx.x & 31;
    const int warp = threadIdx.x >> 5;
    const int wx = warp & 1;
    const int wy = warp >> 1;
    const int x0 = blockIdx.x * 128 + wx * 64 + lane * 2;  // even
    const int y0 = blockIdx.y * 32 + wy * 8;
    const int b  = blockIdx.z;
    const float* img = in + (size_t)b * (IMG_H * IMG_W);

    u64 acc[8];
    #pragma unroll
    for (int r = 0; r < 8; ++r) acc[r] = 0ull;

    // Per input row: ga[j] = in[gy][x0-8+j], j=0..17. x0 even -> float2 aligned.
    const bool xfast = (x0 >= 8) && (x0 <= IMG_W - 10);

    #pragma unroll
    for (int g = 0; g < 22; ++g) {
        const int gy = y0 - 7 + g;
        if (gy >= 0 && gy < IMG_H) {                 // uniform across block
            const float* rowp = img + (size_t)gy * IMG_W;
            float ga[18];
            if (xfast) {
                #pragma unroll
                for (int i = 0; i < 9; ++i) {
                    float2 t = *reinterpret_cast<const float2*>(rowp + x0 - 8 + 2 * i);
                    ga[2 * i] = t.x; ga[2 * i + 1] = t.y;
                }
            } else {
                #pragma unroll
                for (int j = 0; j < 18; ++j) {
                    int gx = x0 - 8 + j;
                    ga[j] = (gx >= 0 && gx < IMG_W) ? rowp[gx] : 0.0f;
                }
            }

            // Horizontal fold: h[e] = (in[x0-e]+in[x0+e], in[x0+1-e]+in[x0+1+e]).
            u64 h[8];
            h[0] = pack2(ga[8], ga[9]);
            h[1] = pack2(ga[7] + ga[9],  ga[8] + ga[10]);
            h[2] = add2(pack2(ga[6],  ga[7]),  pack2(ga[10], ga[11]));
            h[3] = pack2(ga[5] + ga[11], ga[6] + ga[12]);
            h[4] = add2(pack2(ga[4],  ga[5]),  pack2(ga[12], ga[13]));
            h[5] = pack2(ga[3] + ga[13], ga[4] + ga[14]);
            h[6] = add2(pack2(ga[2],  ga[3]),  pack2(ga[14], ga[15]));
            h[7] = pack2(ga[1] + ga[15], ga[2] + ga[16]);

            // Input row gy feeds output row y0+r with dy = g - r in [0,14].
            // Weight row index folds by dy-symmetry: wr = min(dy, 14-dy) <= 7.
            #pragma unroll
            for (int r = 0; r < 8; ++r) {
                const int dy = g - r;                 // compile-time after unroll
                if (dy >= 0 && dy <= 14) {
                    const int wr = (dy <= 7) ? dy : 14 - dy;
                    fma2(acc[r], h[0], wreg[wr][0]);
                    fma2(acc[r], h[1], wreg[wr][1]);
                    fma2(acc[r], h[2], wreg[wr][2]);
                    fma2(acc[r], h[3], wreg[wr][3]);
                    fma2(acc[r], h[4], wreg[wr][4]);
                    fma2(acc[r], h[5], wreg[wr][5]);
                    fma2(acc[r], h[6], wreg[wr][6]);
                    fma2(acc[r], h[7], wreg[wr][7]);
                }
            }
        }
    }

    // Fused roll: out[b, y, (x + s) & 1023] = conv[b, y, x].
    #pragma unroll
    for (int r = 0; r < 8; ++r) {
        const int y = y0 + r;
        const int s = shifts[b * IMG_H + y];
        float* orow = out + ((size_t)b * IMG_H + y) * IMG_W;
        float lo, hi; unpack2(acc[r], lo, hi);
        int c = (x0 + s) & (IMG_W - 1);
        if ((s & 1) == 0) {
            // even shift: c even -> aligned float2, never straddles the wrap
            *reinterpret_cast<float2*>(orow + c) = make_float2(lo, hi);
        } else {
            orow[c] = lo;
            orow[(c + 1) & (IMG_W - 1)] = hi;
        }
    }
}

extern "C" void kernel_launch(void* const* d_in, const int* in_sizes, int n_in,
                              void* d_out, int out_size) {
    const float* img = nullptr;
    const float* kern = nullptr;
    const int*   shifts = nullptr;
    for (int i = 0; i < n_in; ++i) {
        if (in_sizes[i] == NB * IMG_H * IMG_W)      img    = (const float*)d_in[i];
        else if (in_sizes[i] == KS * KS)            kern   = (const float*)d_in[i];
        else if (in_sizes[i] == NB * IMG_H)         shifts = (const int*)d_in[i];
    }
    dim3 grid(IMG_W / 128, IMG_H / 32, NB);
    stem_conv_roll<<<grid, 256>>>(img, kern, shifts, (float*)d_out);
}

// round 5
// speedup vs baseline: 1.6823x; 1.6823x over previous
#include <cuda_runtime.h>
#include <cuda_bf16.h>

#define IMG_W 1024
#define IMG_H 1024
#define KS 15
#define NB 32

typedef unsigned long long u64;

// ---- packed fp32x2 helpers (Blackwell, PTX-only) ----
__device__ __forceinline__ u64 pack2(float lo, float hi) {
    u64 r;
    asm("mov.b64 %0, {%1, %2};" : "=l"(r) : "f"(lo), "f"(hi));
    return r;
}
__device__ __forceinline__ void unpack2(u64 v, float& lo, float& hi) {
    asm("mov.b64 {%0, %1}, %2;" : "=f"(lo), "=f"(hi) : "l"(v));
}
__device__ __forceinline__ void fma2(u64& d, u64 a, u64 b) {
    asm("fma.rn.f32x2 %0, %1, %2, %3;" : "=l"(d) : "l"(a), "l"(b), "l"(d));
}
__device__ __forceinline__ u64 add2(u64 a, u64 b) {
    u64 r;
    asm("add.rn.f32x2 %0, %1, %2;" : "=l"(r) : "l"(a), "l"(b));
    return r;
}

// Thread: 2 px (one f32x2 pair) x 8 output rows. Lanes x-contiguous:
// warp covers 64 consecutive px. Block 256 thr = 8 warps: 2 in x, 4 in y.
// Block tile: 128 px (x) * 32 rows (y). Grid (8, 32, 32).
//
// Weights: Airy kernel symmetric in dx AND dy -> 8 folded rows x 8 pairs.
// Rows 0..2 (serving dy in {0,1,2,12,13,14}) are preloaded from SMEM into
// 48 registers (smem-sourced loads are not rematerializable, unlike __ldg);
// rows 3..7 stay in smem and are fetched per-block via LDS.128.
// __launch_bounds__(256, 2): cap 128 regs -> 2 CTAs/SM = 16 warps.
__global__ __launch_bounds__(256, 2) void stem_conv_roll(
    const float* __restrict__ in, const float* __restrict__ kern,
    const int* __restrict__ shifts, float* __restrict__ out)
{
    // Folded weights: sk[wr*8 + e] = (w,w), w = k[wr][7+e], wr = 0..7.
    __shared__ u64 sk[8 * 8];
    if (threadIdx.x < 64) {
        int wr = threadIdx.x >> 3, e = threadIdx.x & 7;
        float w = kern[wr * KS + 7 + e];
        sk[threadIdx.x] = pack2(w, w);
    }
    __syncthreads();

    // Register-resident copies of folded rows 0..2 (sticky: sourced from smem).
    u64 wr0[8], wr1[8], wr2[8];
    #pragma unroll
    for (int e = 0; e < 8; ++e) { wr0[e] = sk[0 * 8 + e]; wr1[e] = sk[1 * 8 + e]; wr2[e] = sk[2 * 8 + e]; }

    const int lane = threadIdx.x & 31;
    const int warp = threadIdx.x >> 5;
    const int wx = warp & 1;
    const int wy = warp >> 1;
    const int x0 = blockIdx.x * 128 + wx * 64 + lane * 2;  // even
    const int y0 = blockIdx.y * 32 + wy * 8;
    const int b  = blockIdx.z;
    const float* img = in + (size_t)b * (IMG_H * IMG_W);

    u64 acc[8];
    #pragma unroll
    for (int r = 0; r < 8; ++r) acc[r] = 0ull;

    // Per input row: ga[j] = in[gy][x0-8+j], j=0..17. x0 even -> float2 aligned.
    const bool xfast = (x0 >= 8) && (x0 <= IMG_W - 10);

    #pragma unroll
    for (int g = 0; g < 22; ++g) {
        const int gy = y0 - 7 + g;
        if (gy >= 0 && gy < IMG_H) {                 // uniform across block
            const float* rowp = img + (size_t)gy * IMG_W;
            float ga[18];
            if (xfast) {
                #pragma unroll
                for (int i = 0; i < 9; ++i) {
                    float2 t = *reinterpret_cast<const float2*>(rowp + x0 - 8 + 2 * i);
                    ga[2 * i] = t.x; ga[2 * i + 1] = t.y;
                }
            } else {
                #pragma unroll
                for (int j = 0; j < 18; ++j) {
                    int gx = x0 - 8 + j;
                    ga[j] = (gx >= 0 && gx < IMG_W) ? rowp[gx] : 0.0f;
                }
            }

            // Horizontal fold: h[e] = (in[x0-e]+in[x0+e], in[x0+1-e]+in[x0+1+e]).
            u64 h[8];
            h[0] = pack2(ga[8], ga[9]);
            h[1] = pack2(ga[7] + ga[9],  ga[8] + ga[10]);
            h[2] = add2(pack2(ga[6],  ga[7]),  pack2(ga[10], ga[11]));
            h[3] = pack2(ga[5] + ga[11], ga[6] + ga[12]);
            h[4] = add2(pack2(ga[4],  ga[5]),  pack2(ga[12], ga[13]));
            h[5] = pack2(ga[3] + ga[13], ga[4] + ga[14]);
            h[6] = add2(pack2(ga[2],  ga[3]),  pack2(ga[14], ga[15]));
            h[7] = pack2(ga[1] + ga[15], ga[2] + ga[16]);

            // Input row gy feeds output row y0+r with dy = g - r in [0,14].
            // Folded weight row wr = min(dy, 14-dy); wr<=2 comes from registers.
            #pragma unroll
            for (int r = 0; r < 8; ++r) {
                const int dy = g - r;                 // compile-time after unroll
                if (dy >= 0 && dy <= 14) {
                    const int wr = (dy <= 7) ? dy : 14 - dy;
                    if (wr == 0) {
                        #pragma unroll
                        for (int e = 0; e < 8; ++e) fma2(acc[r], h[e], wr0[e]);
                    } else if (wr == 1) {
                        #pragma unroll
                        for (int e = 0; e < 8; ++e) fma2(acc[r], h[e], wr1[e]);
                    } else if (wr == 2) {
                        #pragma unroll
                        for (int e = 0; e < 8; ++e) fma2(acc[r], h[e], wr2[e]);
                    } else {
                        const u64* kw = &sk[wr * 8];
                        ulonglong2 w01 = *reinterpret_cast<const ulonglong2*>(kw + 0);
                        ulonglong2 w23 = *reinterpret_cast<const ulonglong2*>(kw + 2);
                        ulonglong2 w45 = *reinterpret_cast<const ulonglong2*>(kw + 4);
                        ulonglong2 w67 = *reinterpret_cast<const ulonglong2*>(kw + 6);
                        fma2(acc[r], h[0], w01.x);
                        fma2(acc[r], h[1], w01.y);
                        fma2(acc[r], h[2], w23.x);
                        fma2(acc[r], h[3], w23.y);
                        fma2(acc[r], h[4], w45.x);
                        fma2(acc[r], h[5], w45.y);
                        fma2(acc[r], h[6], w67.x);
                        fma2(acc[r], h[7], w67.y);
                    }
                }
            }
        }
    }

    // Fused roll: out[b, y, (x + s) & 1023] = conv[b, y, x].
    #pragma unroll
    for (int r = 0; r < 8; ++r) {
        const int y = y0 + r;
        const int s = shifts[b * IMG_H + y];
        float* orow = out + ((size_t)b * IMG_H + y) * IMG_W;
        float lo, hi; unpack2(acc[r], lo, hi);
        int c = (x0 + s) & (IMG_W - 1);
        if ((s & 1) == 0) {
            // even shift: c even -> aligned float2, never straddles the wrap
            *reinterpret_cast<float2*>(orow + c) = make_float2(lo, hi);
        } else {
            orow[c] = lo;
            orow[(c + 1) & (IMG_W - 1)] = hi;
        }
    }
}

extern "C" void kernel_launch(void* const* d_in, const int* in_sizes, int n_in,
                              void* d_out, int out_size) {
    const float* img = nullptr;
    const float* kern = nullptr;
    const int*   shifts = nullptr;
    for (int i = 0; i < n_in; ++i) {
        if (in_sizes[i] == NB * IMG_H * IMG_W)      img    = (const float*)d_in[i];
        else if (in_sizes[i] == KS * KS)            kern   = (const float*)d_in[i];
        else if (in_sizes[i] == NB * IMG_H)         shifts = (const int*)d_in[i];
    }
    dim3 grid(IMG_W / 128, IMG_H / 32, NB);
    stem_conv_roll<<<grid, 256>>>(img, kern, shifts, (float*)d_out);
}

// round 6
// speedup vs baseline: 1.9463x; 1.1569x over previous
#include <cuda_runtime.h>
#include <cuda_bf16.h>

#define IMG_W 1024
#define IMG_H 1024
#define KS 15
#define NB 32

typedef unsigned long long u64;

// ---- packed fp32x2 helpers (Blackwell, PTX-only) ----
__device__ __forceinline__ u64 pack2(float lo, float hi) {
    u64 r;
    asm("mov.b64 %0, {%1, %2};" : "=l"(r) : "f"(lo), "f"(hi));
    return r;
}
__device__ __forceinline__ void unpack2(u64 v, float& lo, float& hi) {
    asm("mov.b64 {%0, %1}, %2;" : "=f"(lo), "=f"(hi) : "l"(v));
}
__device__ __forceinline__ void fma2(u64& d, u64 a, u64 b) {
    asm("fma.rn.f32x2 %0, %1, %2, %3;" : "=l"(d) : "l"(a), "l"(b), "l"(d));
}
__device__ __forceinline__ u64 add2(u64 a, u64 b) {
    u64 r;
    asm("add.rn.f32x2 %0, %1, %2;" : "=l"(r) : "l"(a), "l"(b));
    return r;
}

// Thread: 4 px (two f32x2 pairs) x 8 output rows. Lanes x-contiguous:
// warp covers 128 consecutive px. Block 256 thr = 8 warps: 2 in x, 4 in y.
// Block tile: 256 px (x) * 32 rows (y). Grid (4, 32, 32).
//
// Weights: Airy kernel symmetric in dx AND dy -> 8 folded rows x 8 (w,w)
// pairs in smem; each 4xLDS.128 weight fetch now feeds 16 FFMA2 (2 pairs).
// Input window per row: 20 floats, 16B-aligned -> 5x LDG.128.
__global__ __launch_bounds__(256, 2) void stem_conv_roll(
    const float* __restrict__ in, const float* __restrict__ kern,
    const int* __restrict__ shifts, float* __restrict__ out)
{
    // Folded weights: sk[wr*8 + e] = (w,w), w = k[wr][7+e], wr = 0..7.
    __shared__ u64 sk[8 * 8];
    if (threadIdx.x < 64) {
        int wr = threadIdx.x >> 3, e = threadIdx.x & 7;
        float w = kern[wr * KS + 7 + e];
        sk[threadIdx.x] = pack2(w, w);
    }
    __syncthreads();

    const int lane = threadIdx.x & 31;
    const int warp = threadIdx.x >> 5;
    const int wx = warp & 1;
    const int wy = warp >> 1;
    const int x0 = blockIdx.x * 256 + wx * 128 + lane * 4;  // multiple of 4
    const int y0 = blockIdx.y * 32 + wy * 8;
    const int b  = blockIdx.z;
    const float* img = in + (size_t)b * (IMG_H * IMG_W);

    u64 acc0[8], acc1[8];
    #pragma unroll
    for (int r = 0; r < 8; ++r) { acc0[r] = 0ull; acc1[r] = 0ull; }

    // Per input row: ga[j] = in[gy][x0-8+j], j=0..19. x0 mult of 4 ->
    // (x0-8) is 16B-aligned -> 5x float4 loads.
    const bool xfast = (x0 >= 8) && (x0 <= IMG_W - 12);

    #pragma unroll
    for (int g = 0; g < 22; ++g) {
        const int gy = y0 - 7 + g;
        if (gy >= 0 && gy < IMG_H) {                 // uniform across block
            const float* rowp = img + (size_t)gy * IMG_W;
            float ga[20];
            if (xfast) {
                #pragma unroll
                for (int v = 0; v < 5; ++v) {
                    float4 t = *reinterpret_cast<const float4*>(rowp + x0 - 8 + 4 * v);
                    ga[4*v+0] = t.x; ga[4*v+1] = t.y; ga[4*v+2] = t.z; ga[4*v+3] = t.w;
                }
            } else {
                #pragma unroll
                for (int j = 0; j < 20; ++j) {
                    int gx = x0 - 8 + j;
                    ga[j] = (gx >= 0 && gx < IMG_W) ? rowp[gx] : 0.0f;
                }
            }

            // Horizontal folds for pair0 (center ga[8],ga[9]) and
            // pair1 (center ga[10],ga[11]).
            u64 h0[8], h1[8];
            h0[0] = pack2(ga[8], ga[9]);
            h0[1] = pack2(ga[7] + ga[9],  ga[8] + ga[10]);
            h0[2] = add2(pack2(ga[6],  ga[7]),  pack2(ga[10], ga[11]));
            h0[3] = pack2(ga[5] + ga[11], ga[6] + ga[12]);
            h0[4] = add2(pack2(ga[4],  ga[5]),  pack2(ga[12], ga[13]));
            h0[5] = pack2(ga[3] + ga[13], ga[4] + ga[14]);
            h0[6] = add2(pack2(ga[2],  ga[3]),  pack2(ga[14], ga[15]));
            h0[7] = pack2(ga[1] + ga[15], ga[2] + ga[16]);

            h1[0] = pack2(ga[10], ga[11]);
            h1[1] = pack2(ga[9]  + ga[11], ga[10] + ga[12]);
            h1[2] = add2(pack2(ga[8],  ga[9]),  pack2(ga[12], ga[13]));
            h1[3] = pack2(ga[7]  + ga[13], ga[8]  + ga[14]);
            h1[4] = add2(pack2(ga[6],  ga[7]),  pack2(ga[14], ga[15]));
            h1[5] = pack2(ga[5]  + ga[15], ga[6]  + ga[16]);
            h1[6] = add2(pack2(ga[4],  ga[5]),  pack2(ga[16], ga[17]));
            h1[7] = pack2(ga[3]  + ga[17], ga[4]  + ga[18]);

            // Input row gy feeds output row y0+r with dy = g - r in [0,14].
            // Folded weight row wr = min(dy, 14-dy); one fetch feeds both pairs.
            #pragma unroll
            for (int r = 0; r < 8; ++r) {
                const int dy = g - r;                 // compile-time after unroll
                if (dy >= 0 && dy <= 14) {
                    const int wr = (dy <= 7) ? dy : 14 - dy;
                    const u64* kw = &sk[wr * 8];
                    ulonglong2 w01 = *reinterpret_cast<const ulonglong2*>(kw + 0);
                    ulonglong2 w23 = *reinterpret_cast<const ulonglong2*>(kw + 2);
                    ulonglong2 w45 = *reinterpret_cast<const ulonglong2*>(kw + 4);
                    ulonglong2 w67 = *reinterpret_cast<const ulonglong2*>(kw + 6);
                    fma2(acc0[r], h0[0], w01.x);  fma2(acc1[r], h1[0], w01.x);
                    fma2(acc0[r], h0[1], w01.y);  fma2(acc1[r], h1[1], w01.y);
                    fma2(acc0[r], h0[2], w23.x);  fma2(acc1[r], h1[2], w23.x);
                    fma2(acc0[r], h0[3], w23.y);  fma2(acc1[r], h1[3], w23.y);
                    fma2(acc0[r], h0[4], w45.x);  fma2(acc1[r], h1[4], w45.x);
                    fma2(acc0[r], h0[5], w45.y);  fma2(acc1[r], h1[5], w45.y);
                    fma2(acc0[r], h0[6], w67.x);  fma2(acc1[r], h1[6], w67.x);
                    fma2(acc0[r], h0[7], w67.y);  fma2(acc1[r], h1[7], w67.y);
                }
            }
        }
    }

    // Fused roll: out[b, y, (x + s) & 1023] = conv[b, y, x].
    #pragma unroll
    for (int r = 0; r < 8; ++r) {
        const int y = y0 + r;
        const int s = shifts[b * IMG_H + y];
        float* orow = out + ((size_t)b * IMG_H + y) * IMG_W;
        float lo0, hi0, lo1, hi1;
        unpack2(acc0[r], lo0, hi0);
        unpack2(acc1[r], lo1, hi1);
        int c0 = (x0 + s) & (IMG_W - 1);
        int c1 = (x0 + 2 + s) & (IMG_W - 1);
        if ((s & 1) == 0) {
            // even shift: c0,c1 even -> aligned float2, never straddle the wrap
            *reinterpret_cast<float2*>(orow + c0) = make_float2(lo0, hi0);
            *reinterpret_cast<float2*>(orow + c1) = make_float2(lo1, hi1);
        } else {
            orow[c0] = lo0;
            orow[(c0 + 1) & (IMG_W - 1)] = hi0;
            orow[c1] = lo1;
            orow[(c1 + 1) & (IMG_W - 1)] = hi1;
        }
    }
}

extern "C" void kernel_launch(void* const* d_in, const int* in_sizes, int n_in,
                              void* d_out, int out_size) {
    const float* img = nullptr;
    const float* kern = nullptr;
    const int*   shifts = nullptr;
    for (int i = 0; i < n_in; ++i) {
        if (in_sizes[i] == NB * IMG_H * IMG_W)      img    = (const float*)d_in[i];
        else if (in_sizes[i] == KS * KS)            kern   = (const float*)d_in[i];
        else if (in_sizes[i] == NB * IMG_H)         shifts = (const int*)d_in[i];
    }
    dim3 grid(IMG_W / 256, IMG_H / 32, NB);
    stem_conv_roll<<<grid, 256>>>(img, kern, shifts, (float*)d_out);
}

// round 7
// speedup vs baseline: 2.9269x; 1.5039x over previous
#include <cuda_runtime.h>
#include <cuda_bf16.h>

#define IMG_W 1024
#define IMG_H 1024
#define KS 15
#define NB 32

// Input tile staged in smem: x covers [bx*256-8, bx*256+264) = 272 floats,
// y covers [by*32-7, by*32+39) = 46 rows. Zero-padded outside the image.
#define TILE_W 272
#define TILE_H 46
#define SMEM_BYTES (512 + TILE_W * TILE_H * 4)

typedef unsigned long long u64;

// ---- packed fp32x2 helpers (Blackwell, PTX-only) ----
__device__ __forceinline__ u64 pack2(float lo, float hi) {
    u64 r;
    asm("mov.b64 %0, {%1, %2};" : "=l"(r) : "f"(lo), "f"(hi));
    return r;
}
__device__ __forceinline__ void unpack2(u64 v, float& lo, float& hi) {
    asm("mov.b64 {%0, %1}, %2;" : "=f"(lo), "=f"(hi) : "l"(v));
}
__device__ __forceinline__ void fma2(u64& d, u64 a, u64 b) {
    asm("fma.rn.f32x2 %0, %1, %2, %3;" : "=l"(d) : "l"(a), "l"(b), "l"(d));
}
__device__ __forceinline__ u64 add2(u64 a, u64 b) {
    u64 r;
    asm("add.rn.f32x2 %0, %1, %2;" : "=l"(r) : "l"(a), "l"(b));
    return r;
}

// Thread: 4 px (two f32x2 pairs) x 8 output rows. Block 256 thr = 8 warps:
// 2 in x, 4 in y. Block tile: 256 px * 32 rows. Grid (4, 32, 32).
// Weights (dx+dy folded Airy symmetry): 8 rows x 8 (w,w) pairs in smem.
// Input read from the staged smem tile -> branch-free hot loop, LDS lat 29.
__global__ __launch_bounds__(256, 2) void stem_conv_roll(
    const float* __restrict__ in, const float* __restrict__ kern,
    const int* __restrict__ shifts, float* __restrict__ out)
{
    extern __shared__ char dynsmem[];
    u64*   sk  = reinterpret_cast<u64*>(dynsmem);          // 64 * 8B = 512B
    float* sIn = reinterpret_cast<float*>(dynsmem + 512);  // [TILE_H][TILE_W]

    const int tid = threadIdx.x;
    const int b   = blockIdx.z;
    const float* img = in + (size_t)b * (IMG_H * IMG_W);

    // Folded weights: sk[wr*8 + e] = (w,w), w = k[wr][7+e], wr = 0..7.
    if (tid < 64) {
        int wr = tid >> 3, e = tid & 7;
        float w = kern[wr * KS + 7 + e];
        sk[tid] = pack2(w, w);
    }

    // ---- Stage input tile (float4 granularity, zero-padded) ----
    const int gxb = blockIdx.x * 256 - 8;   // (gxb*4B) is 16B-aligned
    const int gyb = blockIdx.y * 32 - 7;
    for (int idx = tid; idx < TILE_H * (TILE_W / 4); idx += 256) {
        const int ry  = idx / (TILE_W / 4);
        const int rx4 = idx - ry * (TILE_W / 4);
        const int gy  = gyb + ry;
        const int gx  = gxb + rx4 * 4;
        float4 v = make_float4(0.f, 0.f, 0.f, 0.f);
        if (gy >= 0 && gy < IMG_H) {
            const float* rowp = img + (size_t)gy * IMG_W;
            if (gx >= 0 && gx <= IMG_W - 4) {
                v = *reinterpret_cast<const float4*>(rowp + gx);
            } else {
                if (gx + 0 >= 0 && gx + 0 < IMG_W) v.x = rowp[gx + 0];
                if (gx + 1 >= 0 && gx + 1 < IMG_W) v.y = rowp[gx + 1];
                if (gx + 2 >= 0 && gx + 2 < IMG_W) v.z = rowp[gx + 2];
                if (gx + 3 >= 0 && gx + 3 < IMG_W) v.w = rowp[gx + 3];
            }
        }
        *reinterpret_cast<float4*>(sIn + ry * TILE_W + rx4 * 4) = v;
    }
    __syncthreads();

    const int lane = tid & 31;
    const int warp = tid >> 5;
    const int wx = warp & 1;
    const int wy = warp >> 1;
    const int xl = wx * 128 + lane * 4;       // local x of first px (mult of 4)
    const int x0 = blockIdx.x * 256 + xl;
    const int y0 = blockIdx.y * 32 + wy * 8;

    u64 acc0[8], acc1[8];
    #pragma unroll
    for (int r = 0; r < 8; ++r) { acc0[r] = 0ull; acc1[r] = 0ull; }

    // ga[j] = tile[yl + g][xl + j], j = 0..19  (== in[gy][x0-8+j], zero-padded)
    const float* tbase = sIn + wy * 8 * TILE_W + xl;

    #pragma unroll
    for (int g = 0; g < 22; ++g) {
        const float* trow = tbase + g * TILE_W;
        float ga[20];
        #pragma unroll
        for (int v = 0; v < 5; ++v) {
            float4 t = *reinterpret_cast<const float4*>(trow + 4 * v);
            ga[4*v+0] = t.x; ga[4*v+1] = t.y; ga[4*v+2] = t.z; ga[4*v+3] = t.w;
        }

        // Horizontal folds for pair0 (center ga[8],ga[9]) and pair1 (ga[10],ga[11]).
        u64 h0[8], h1[8];
        h0[0] = pack2(ga[8], ga[9]);
        h0[1] = pack2(ga[7] + ga[9],  ga[8] + ga[10]);
        h0[2] = add2(pack2(ga[6],  ga[7]),  pack2(ga[10], ga[11]));
        h0[3] = pack2(ga[5] + ga[11], ga[6] + ga[12]);
        h0[4] = add2(pack2(ga[4],  ga[5]),  pack2(ga[12], ga[13]));
        h0[5] = pack2(ga[3] + ga[13], ga[4] + ga[14]);
        h0[6] = add2(pack2(ga[2],  ga[3]),  pack2(ga[14], ga[15]));
        h0[7] = pack2(ga[1] + ga[15], ga[2] + ga[16]);

        h1[0] = pack2(ga[10], ga[11]);
        h1[1] = pack2(ga[9]  + ga[11], ga[10] + ga[12]);
        h1[2] = add2(pack2(ga[8],  ga[9]),  pack2(ga[12], ga[13]));
        h1[3] = pack2(ga[7]  + ga[13], ga[8]  + ga[14]);
        h1[4] = add2(pack2(ga[6],  ga[7]),  pack2(ga[14], ga[15]));
        h1[5] = pack2(ga[5]  + ga[15], ga[6]  + ga[16]);
        h1[6] = add2(pack2(ga[4],  ga[5]),  pack2(ga[16], ga[17]));
        h1[7] = pack2(ga[3]  + ga[17], ga[4]  + ga[18]);

        // dy = g - r in [0,14]; folded weight row wr = min(dy, 14-dy).
        #pragma unroll
        for (int r = 0; r < 8; ++r) {
            const int dy = g - r;                 // compile-time after unroll
            if (dy >= 0 && dy <= 14) {
                const int wr = (dy <= 7) ? dy : 14 - dy;
                const u64* kw = &sk[wr * 8];
                ulonglong2 w01 = *reinterpret_cast<const ulonglong2*>(kw + 0);
                ulonglong2 w23 = *reinterpret_cast<const ulonglong2*>(kw + 2);
                ulonglong2 w45 = *reinterpret_cast<const ulonglong2*>(kw + 4);
                ulonglong2 w67 = *reinterpret_cast<const ulonglong2*>(kw + 6);
                fma2(acc0[r], h0[0], w01.x);  fma2(acc1[r], h1[0], w01.x);
                fma2(acc0[r], h0[1], w01.y);  fma2(acc1[r], h1[1], w01.y);
                fma2(acc0[r], h0[2], w23.x);  fma2(acc1[r], h1[2], w23.x);
                fma2(acc0[r], h0[3], w23.y);  fma2(acc1[r], h1[3], w23.y);
                fma2(acc0[r], h0[4], w45.x);  fma2(acc1[r], h1[4], w45.x);
                fma2(acc0[r], h0[5], w45.y);  fma2(acc1[r], h1[5], w45.y);
                fma2(acc0[r], h0[6], w67.x);  fma2(acc1[r], h1[6], w67.x);
                fma2(acc0[r], h0[7], w67.y);  fma2(acc1[r], h1[7], w67.y);
            }
        }
    }

    // Fused roll: out[b, y, (x + s) & 1023] = conv[b, y, x].
    #pragma unroll
    for (int r = 0; r < 8; ++r) {
        const int y = y0 + r;
        const int s = shifts[b * IMG_H + y];
        float* orow = out + ((size_t)b * IMG_H + y) * IMG_W;
        float lo0, hi0, lo1, hi1;
        unpack2(acc0[r], lo0, hi0);
        unpack2(acc1[r], lo1, hi1);
        int c0 = (x0 + s) & (IMG_W - 1);
        int c1 = (x0 + 2 + s) & (IMG_W - 1);
        if ((s & 1) == 0) {
            // even shift: c0,c1 even -> aligned float2, never straddle the wrap
            *reinterpret_cast<float2*>(orow + c0) = make_float2(lo0, hi0);
            *reinterpret_cast<float2*>(orow + c1) = make_float2(lo1, hi1);
        } else {
            orow[c0] = lo0;
            orow[(c0 + 1) & (IMG_W - 1)] = hi0;
            orow[c1] = lo1;
            orow[(c1 + 1) & (IMG_W - 1)] = hi1;
        }
    }
}

extern "C" void kernel_launch(void* const* d_in, const int* in_sizes, int n_in,
                              void* d_out, int out_size) {
    const float* img = nullptr;
    const float* kern = nullptr;
    const int*   shifts = nullptr;
    for (int i = 0; i < n_in; ++i) {
        if (in_sizes[i] == NB * IMG_H * IMG_W)      img    = (const float*)d_in[i];
        else if (in_sizes[i] == KS * KS)            kern   = (const float*)d_in[i];
        else if (in_sizes[i] == NB * IMG_H)         shifts = (const int*)d_in[i];
    }
    cudaFuncSetAttribute(stem_conv_roll,
                         cudaFuncAttributeMaxDynamicSharedMemorySize, SMEM_BYTES);
    dim3 grid(IMG_W / 256, IMG_H / 32, NB);
    stem_conv_roll<<<grid, 256, SMEM_BYTES>>>(img, kern, shifts, (float*)d_out);
}